// round 15
// baseline (speedup 1.0000x reference)
#include <cuda_runtime.h>
#include <cuda_bf16.h>
#include <math.h>
#include <stdint.h>

#define NROWS 32768
#define DDIM  1024
#define NGD   1024
#define NLD   256
#define NCOMB 1280
#define NM    (NROWS * DDIM)

typedef __nv_bfloat16 bf;

// ---------------- warp MMA primitives (plain sm_80+ PTX, no 'a' features) --
__device__ __forceinline__ uint32_t smem_u32(const void* p) {
    uint32_t a;
    asm("{ .reg .u64 t; cvta.to.shared.u64 t, %1; cvt.u32.u64 %0, t; }" : "=r"(a) : "l"(p));
    return a;
}
__device__ __forceinline__ void ldsm4(uint32_t addr, uint32_t* f) {
    asm volatile("ldmatrix.sync.aligned.m8n8.x4.shared.b16 {%0,%1,%2,%3}, [%4];"
                 : "=r"(f[0]), "=r"(f[1]), "=r"(f[2]), "=r"(f[3]) : "r"(addr));
}
__device__ __forceinline__ void mma16816(float* c, const uint32_t* a, uint32_t b0, uint32_t b1) {
    asm volatile("mma.sync.aligned.m16n8k16.row.col.f32.bf16.bf16.f32 "
                 "{%0,%1,%2,%3}, {%4,%5,%6,%7}, {%8,%9}, {%0,%1,%2,%3};"
                 : "+f"(c[0]), "+f"(c[1]), "+f"(c[2]), "+f"(c[3])
                 : "r"(a[0]), "r"(a[1]), "r"(a[2]), "r"(a[3]), "r"(b0), "r"(b1));
}
__device__ __forceinline__ void cp16(uint32_t dst, const void* src) {
    asm volatile("cp.async.cg.shared.global [%0], [%1], 16;" :: "r"(dst), "l"(src));
}
#define CP_COMMIT() asm volatile("cp.async.commit_group;" ::: "memory")
#define CP_WAIT(n)  asm volatile("cp.async.wait_group %0;" :: "n"(n) : "memory")

__device__ __forceinline__ void split2(float x, bf& h, bf& l) {
    h = __float2bfloat16(x);
    l = __float2bfloat16(x - __bfloat162float(h));
}

// ---------------- scratch ---------------------------------------------------
__device__ float  g_zp[NM];
__device__ float  g_nn[NM];
__device__ float  g_gate[NM];
__device__ float  g_S[(size_t)NROWS * NCOMB];
__device__ float  g_comb[NCOMB * DDIM];
__device__ float  g_cnts[NCOMB];
__device__ int    g_cnt_i[NCOMB];
__device__ int    g_cur[NCOMB];
__device__ int    g_off[NCOMB];
__device__ int    g_list[2 * NROWS];
__device__ int    g_idx[2 * NROWS];
__device__ double g_acc[3];

__device__ bf b_z[2][NM];
__device__ bf b_h[2][NM];
__device__ bf b_zp[2][NM];
__device__ bf b_nn[2][NM];
__device__ bf b_zn[2][NM];
__device__ bf b_S[2][(size_t)NROWS * NCOMB];
__device__ bf b_W1T[2][DDIM * DDIM];
__device__ bf b_W2T[2][DDIM * DDIM];
__device__ bf b_WgT[2][DDIM * DDIM];
__device__ bf b_gd[2][NGD * DDIM];
__device__ bf b_ld[2][NLD * DDIM];
__device__ bf b_comb[2][NCOMB * DDIM];
__device__ bf b_combT[2][DDIM * NCOMB];

// ---------------- small kernels --------------------------------------------
__global__ void init_kernel() {
    int i = blockIdx.x * blockDim.x + threadIdx.x;
    if (i < NCOMB) { g_cnt_i[i] = 0; g_cur[i] = 0; }
    if (i < 3)     g_acc[i] = 0.0;
}

__global__ __launch_bounds__(256)
void conv_split_kernel(const float* __restrict__ src, bf* __restrict__ dh,
                       bf* __restrict__ dl, int n) {
    int i = (blockIdx.x * blockDim.x + threadIdx.x) * 4;
    if (i + 3 < n) {
        float4 v = *reinterpret_cast<const float4*>(&src[i]);
        bf h[4], l[4];
        split2(v.x, h[0], l[0]); split2(v.y, h[1], l[1]);
        split2(v.z, h[2], l[2]); split2(v.w, h[3], l[3]);
        *reinterpret_cast<uint2*>(&dh[i]) = *reinterpret_cast<uint2*>(h);
        *reinterpret_cast<uint2*>(&dl[i]) = *reinterpret_cast<uint2*>(l);
    }
}

// tiled transpose + split: src [R][C] fp32 -> dst [c][r] bf16 hi/lo
__global__ __launch_bounds__(256)
void transconv_kernel(const float* __restrict__ src, int R, int C,
                      bf* __restrict__ dh, bf* __restrict__ dl) {
    __shared__ float t[32][33];
    const int bx = blockIdx.x * 32, by = blockIdx.y * 32;
    const int tx = threadIdx.x & 31, ty = threadIdx.x >> 5;
#pragma unroll
    for (int i = 0; i < 4; i++)
        t[ty + 8 * i][tx] = src[(size_t)(by + ty + 8 * i) * C + bx + tx];
    __syncthreads();
#pragma unroll
    for (int i = 0; i < 4; i++) {
        float x = t[tx][ty + 8 * i];
        bf h, l; split2(x, h, l);
        size_t o = (size_t)(bx + ty + 8 * i) * R + by + tx;
        dh[o] = h; dl[o] = l;
    }
}

// row L2 normalize; optional fp32 out; bf16 hi/lo; optional raw copy; optional
// fused |dot(normalized, UN_row)| accumulation into g_acc[2]
__global__ __launch_bounds__(256)
void rownorm_split_kernel(const float* __restrict__ X, float* __restrict__ Y,
                          bf* __restrict__ Yh, bf* __restrict__ Yl,
                          float* __restrict__ Cpy, const float* __restrict__ UN) {
    __shared__ float red[8];
    const int r = blockIdx.x, tid = threadIdx.x;
    float4 x = *reinterpret_cast<const float4*>(&X[(size_t)r * DDIM + tid * 4]);
    float ss = x.x * x.x + x.y * x.y + x.z * x.z + x.w * x.w;
#pragma unroll
    for (int off = 16; off; off >>= 1) ss += __shfl_down_sync(0xffffffffu, ss, off);
    if ((tid & 31) == 0) red[tid >> 5] = ss;
    __syncthreads();
    if (tid == 0) {
        float s = 0.f;
#pragma unroll
        for (int i = 0; i < 8; i++) s += red[i];
        red[0] = s;
    }
    __syncthreads();
    float inv = 1.f / fmaxf(sqrtf(red[0]), 1e-12f);
    float f[4] = {x.x * inv, x.y * inv, x.z * inv, x.w * inv};
    size_t o = (size_t)r * DDIM + tid * 4;
    if (Y) *reinterpret_cast<float4*>(&Y[o]) = make_float4(f[0], f[1], f[2], f[3]);
    bf h[4], l[4];
#pragma unroll
    for (int i = 0; i < 4; i++) split2(f[i], h[i], l[i]);
    *reinterpret_cast<uint2*>(&Yh[o]) = *reinterpret_cast<uint2*>(h);
    *reinterpret_cast<uint2*>(&Yl[o]) = *reinterpret_cast<uint2*>(l);
    if (Cpy) { Cpy[o] = x.x; Cpy[o + 1] = x.y; Cpy[o + 2] = x.z; Cpy[o + 3] = x.w; }
    if (UN) {
        float4 un = *reinterpret_cast<const float4*>(&UN[o]);
        float p = f[0] * un.x + f[1] * un.y + f[2] * un.z + f[3] * un.w;
#pragma unroll
        for (int off = 16; off; off >>= 1) p += __shfl_down_sync(0xffffffffu, p, off);
        __syncthreads();
        if ((tid & 31) == 0) red[tid >> 5] = p;
        __syncthreads();
        if (tid == 0) {
            float s = 0.f;
#pragma unroll
            for (int i = 0; i < 8; i++) s += red[i];
            atomicAdd(&g_acc[2], (double)fabsf(s));
        }
    }
}

// ---------------- HMMA GEMM (3-stage cp.async, XOR swizzle, 4 warps @64x64) --
// NPROD: 1 = ah*bh, 2 = (ah+al)*bh, 3 = full hi/lo split
enum { EPI_RELU_BIAS = 0, EPI_BIAS = 1, EPI_SIGMOID = 2, EPI_S_LOSS = 3, EPI_ZCLEAN = 4 };

#define TILE_B  8192                 // 128 rows x 64 bytes (32 bf16), swizzled
#define STAGE_B (4 * TILE_B)         // 32768 per stage (slots: Ah, Al, Bh, Bl)
#define SM_TOTAL (3 * STAGE_B)       // 98304 : 2 CTAs/SM

// swizzled byte offset inside a tile: row in [0,128), c16 in [0,4)
__device__ __forceinline__ uint32_t swz(int row, int c16) {
    return (uint32_t)(row * 64 + ((c16 ^ ((row >> 1) & 3)) << 4));
}

// cp.async fill of one 32-wide K-chunk into stage s; loads only tiles NPROD needs
template <int NPROD>
__device__ __forceinline__ void fill_async(
    uint32_t sb, int s,
    const bf* __restrict__ Ah, const bf* __restrict__ Al,
    const bf* __restrict__ Bh, const bf* __restrict__ Bl,
    int m0, int n0, int k0, int K, int tid) {
    const uint32_t base = sb + s * STAGE_B;
#pragma unroll
    for (int t = 0; t < 4; t++) {
        if (t == 1 && NPROD < 2) continue;   // Al unused
        if (t == 3 && NPROD < 3) continue;   // Bl unused
        const bf* gp = (t == 0) ? Ah : (t == 1) ? Al : (t == 2) ? Bh : Bl;
        const int rb = (t < 2) ? m0 : n0;
        const uint32_t tb = base + t * TILE_B;
#pragma unroll
        for (int v = 0; v < 4; v++) {
            int idx = v * 128 + tid;
            int row = idx >> 2, c16 = idx & 3;
            cp16(tb + swz(row, c16), gp + (size_t)(rb + row) * K + k0 + c16 * 8);
        }
    }
    CP_COMMIT();
}

// NPROD-tiered compute of one K-chunk into acc[4][8][4] (warp 64x64)
template <int NPROD>
__device__ __forceinline__ void chunk_mma(float acc[4][8][4], uint32_t base,
                                          int lane, int warp_m, int warp_n) {
    const int arow = warp_m + (lane & 15);
    const int ahi  = lane >> 4;
    const int brow = warp_n + ((lane & 7) | ((lane >> 4) << 3));
    const int bhi  = (lane >> 3) & 1;
#pragma unroll
    for (int ks = 0; ks < 2; ks++) {
        uint32_t bh[16], bl[16];
#pragma unroll
        for (int i = 0; i < 4; i++) {
            uint32_t off = swz(brow + i * 16, ks * 2 + bhi);
            ldsm4(base + 2 * TILE_B + off, bh + 4 * i);
            if (NPROD >= 3) ldsm4(base + 3 * TILE_B + off, bl + 4 * i);
        }
#pragma unroll
        for (int mt = 0; mt < 4; mt++) {
            uint32_t off = swz(arow + mt * 16, ks * 2 + ahi);
            uint32_t ah[4], al[4];
            ldsm4(base + off, ah);
            if (NPROD >= 2) ldsm4(base + TILE_B + off, al);
#pragma unroll
            for (int nt = 0; nt < 8; nt++) {
                mma16816(acc[mt][nt], ah, bh[2 * nt], bh[2 * nt + 1]);
                if (NPROD >= 3) mma16816(acc[mt][nt], ah, bl[2 * nt], bl[2 * nt + 1]);
                if (NPROD >= 2) mma16816(acc[mt][nt], al, bh[2 * nt], bh[2 * nt + 1]);
            }
        }
    }
}

// 3-stage mainloop: one __syncthreads per chunk.
#define GEMM_MAINLOOP(NP, Ahp, Alp, Bhp, Blp, M0, N0, KK)                               \
    do {                                                                                \
        const int nch = (KK) >> 5;                                                      \
        fill_async<NP>(sb, 0, Ahp, Alp, Bhp, Blp, M0, N0, 0, KK, tid);                  \
        fill_async<NP>(sb, 1, Ahp, Alp, Bhp, Blp, M0, N0, 32, KK, tid);                 \
        for (int kc = 0; kc < nch; kc++) {                                              \
            if (kc + 1 < nch) { CP_WAIT(1); } else { CP_WAIT(0); }                      \
            __syncthreads();                                                            \
            if (kc + 2 < nch)                                                           \
                fill_async<NP>(sb, (kc + 2) % 3, Ahp, Alp, Bhp, Blp, M0, N0,            \
                               (kc + 2) << 5, KK, tid);                                 \
            chunk_mma<NP>(acc, sb + (kc % 3) * STAGE_B, lane, warp_m, warp_n);          \
        }                                                                               \
    } while (0)

template <int EPI, int NPROD, bool WF32, bool WSPLIT, bool WMIS>
__global__ __launch_bounds__(128)
void gemm_mma(const bf* __restrict__ Ah, const bf* __restrict__ Al,
              const bf* __restrict__ Bh, const bf* __restrict__ Bl,
              const float* __restrict__ bias, float* __restrict__ Cf,
              bf* __restrict__ Ch, bf* __restrict__ Cl, float* __restrict__ Cm,
              int Ncols, int K,
              const float* __restrict__ e1, const float* __restrict__ e2) {
    extern __shared__ __align__(16) char smem[];
    const uint32_t sb = smem_u32(smem);
    const int tid = threadIdx.x, lane = tid & 31, wid = tid >> 5;
    const int m0 = blockIdx.y * 128, n0 = blockIdx.x * 128;
    const int warp_m = (wid >> 1) * 64, warp_n = (wid & 1) * 64;

    float acc[4][8][4] = {};
    GEMM_MAINLOOP(NPROD, Ah, Al, Bh, Bl, m0, n0, K);

    // ---------------- epilogue ----------------
    double part = 0.0;
#pragma unroll
    for (int mt = 0; mt < 4; mt++) {
        const int r0 = m0 + warp_m + mt * 16 + (lane >> 2);
#pragma unroll
        for (int nt = 0; nt < 8; nt++) {
            const int col = n0 + warp_n + nt * 8 + ((lane & 3) << 1);
            float b2x = 0.f, b2y = 0.f;
            if (EPI == EPI_RELU_BIAS || EPI == EPI_BIAS || EPI == EPI_SIGMOID) {
                float2 bb = *reinterpret_cast<const float2*>(bias + col);
                b2x = bb.x; b2y = bb.y;
            }
#pragma unroll
            for (int h = 0; h < 2; h++) {
                const int row = r0 + h * 8;
                float v0 = acc[mt][nt][2 * h], v1 = acc[mt][nt][2 * h + 1];
                if (EPI == EPI_RELU_BIAS) { v0 = fmaxf(v0 + b2x, 0.f); v1 = fmaxf(v1 + b2y, 0.f); }
                else if (EPI == EPI_BIAS) { v0 += b2x; v1 += b2y; }
                else if (EPI == EPI_SIGMOID) {
                    v0 = 1.f / (1.f + expf(-(v0 + b2x)));
                    v1 = 1.f / (1.f + expf(-(v1 + b2y)));
                }
                const size_t ro = (size_t)row * Ncols + col;
                if (EPI == EPI_ZCLEAN) {
                    float2 z2 = *reinterpret_cast<const float2*>(e1 + ro);
                    float2 q2 = *reinterpret_cast<const float2*>(e2 + ro);
                    v0 = z2.x - q2.x * v0;
                    v1 = z2.y - q2.y * v1;
                }
                if (EPI == EPI_S_LOSS) part += (double)fabsf(v0) + (double)fabsf(v1);
                if (WF32)
                    *reinterpret_cast<float2*>(Cf + ro) = make_float2(v0, v1);
                if (WMIS) { Cm[ro] = v0; Cm[ro + 1] = v1; }
                if (WSPLIT) {
                    bf h0, l0, h1, l1;
                    split2(v0, h0, l0); split2(v1, h1, l1);
                    bf hp[2] = {h0, h1}, lp[2] = {l0, l1};
                    *reinterpret_cast<uint32_t*>(Ch + ro) = *reinterpret_cast<uint32_t*>(hp);
                    *reinterpret_cast<uint32_t*>(Cl + ro) = *reinterpret_cast<uint32_t*>(lp);
                }
            }
        }
    }
    if (EPI == EPI_S_LOSS) {
#pragma unroll
        for (int off = 16; off; off >>= 1) part += __shfl_down_sync(0xffffffffu, part, off);
        if (lane == 0) atomicAdd(&g_acc[(n0 < NGD) ? 0 : 1], part);
    }
}

// ---------------- dual-dict HMMA argmax + count (NPROD=2) --------------------
__global__ __launch_bounds__(128)
void argmax_dual(const bf* __restrict__ Ah, const bf* __restrict__ Al,
                 const bf* __restrict__ Gh, const bf* __restrict__ Gl,
                 const bf* __restrict__ Lh, const bf* __restrict__ Ll,
                 int* __restrict__ idx_out) {
    extern __shared__ __align__(16) char smem[];
    __shared__ float sval[128][2];
    __shared__ int   sidx[128][2];
    const uint32_t sb = smem_u32(smem);
    const int tid = threadIdx.x, lane = tid & 31, wid = tid >> 5;
    const int m0 = blockIdx.x * 128;
    const int warp_m = (wid >> 1) * 64, warp_n = (wid & 1) * 64;

    for (int part = 0; part < 2; part++) {
        const bf* Dh = part ? Lh : Gh;
        const bf* Dl = part ? Ll : Gl;
        const int ncodes = part ? NLD : NGD;

        float bv[8]; int bi[8];
#pragma unroll
        for (int i = 0; i < 8; i++) { bv[i] = -1e30f; bi[i] = 0; }

        for (int n0 = 0; n0 < ncodes; n0 += 128) {
            float acc[4][8][4] = {};
            GEMM_MAINLOOP(2, Ah, Al, Dh, Dl, m0, n0, DDIM);
            __syncthreads();  // reads done before next tile's preload overwrites
#pragma unroll
            for (int mt = 0; mt < 4; mt++)
#pragma unroll
                for (int h = 0; h < 2; h++) {
                    float* bvp = &bv[mt * 2 + h]; int* bip = &bi[mt * 2 + h];
#pragma unroll
                    for (int nt = 0; nt < 8; nt++) {
                        const int col = n0 + warp_n + nt * 8 + ((lane & 3) << 1);
                        float v0 = acc[mt][nt][2 * h], v1 = acc[mt][nt][2 * h + 1];
                        if (v0 > *bvp) { *bvp = v0; *bip = col; }
                        if (v1 > *bvp) { *bvp = v1; *bip = col + 1; }
                    }
                }
        }
#pragma unroll
        for (int i = 0; i < 8; i++) {
            float v = bv[i]; int c = bi[i];
#pragma unroll
            for (int off = 1; off <= 2; off <<= 1) {
                float ov = __shfl_xor_sync(0xffffffffu, v, off);
                int   oc = __shfl_xor_sync(0xffffffffu, c, off);
                if (ov > v || (ov == v && oc < c)) { v = ov; c = oc; }
            }
            if ((lane & 3) == 0) {
                int row = warp_m + (i >> 1) * 16 + (i & 1) * 8 + (lane >> 2);
                sval[row][wid & 1] = v;
                sidx[row][wid & 1] = c;
            }
        }
        __syncthreads();
        {
            float v = sval[tid][0]; int c = sidx[tid][0];
            float ov = sval[tid][1]; int oc = sidx[tid][1];
            if (ov > v || (ov == v && oc < c)) { v = ov; c = oc; }
            idx_out[part * NROWS + m0 + tid] = c;
            atomicAdd(&g_cnt_i[part ? NGD + c : c], 1);
        }
        __syncthreads();
    }
}

// ---------------- scan / fill / gather dict update --------------------------
__global__ __launch_bounds__(256)
void scan_kernel() {
    __shared__ int ws[8];
    const int tid = threadIdx.x, lane = tid & 31, wid = tid >> 5;
    int v[5]; int s = 0;
#pragma unroll
    for (int i = 0; i < 5; i++) { v[i] = g_cnt_i[tid * 5 + i]; s += v[i]; }
    int x = s;
#pragma unroll
    for (int off = 1; off < 32; off <<= 1) {
        int t = __shfl_up_sync(0xffffffffu, x, off);
        if (lane >= off) x += t;
    }
    if (lane == 31) ws[wid] = x;
    __syncthreads();
    if (tid == 0) {
        int a = 0;
#pragma unroll
        for (int w = 0; w < 8; w++) { int t = ws[w]; ws[w] = a; a += t; }
    }
    __syncthreads();
    int run = x - s + ws[wid];
#pragma unroll
    for (int i = 0; i < 5; i++) {
        g_off[tid * 5 + i] = run;
        g_cnts[tid * 5 + i] = (float)v[i];
        run += v[i];
    }
}

__global__ __launch_bounds__(256)
void fill_list_kernel(const int* __restrict__ idx) {
    const int r = blockIdx.x * blockDim.x + threadIdx.x;
    if (r < NROWS) {
        int ig = idx[r];
        int pos = atomicAdd(&g_cur[ig], 1);
        g_list[g_off[ig] + pos] = r;
        int il = NGD + idx[NROWS + r];
        int pos2 = atomicAdd(&g_cur[il], 1);
        g_list[g_off[il] + pos2] = r;
    }
}

__global__ __launch_bounds__(256)
void dictupd_kernel(const float* __restrict__ gd, const float* __restrict__ ld,
                    bf* __restrict__ ch, bf* __restrict__ cl) {
    __shared__ float red[8];
    const int c = blockIdx.x, tid = threadIdx.x;
    const int cnt = g_cnt_i[c], off = g_off[c];
    float4 acc = make_float4(0.f, 0.f, 0.f, 0.f);
    int i = 0;
    for (; i + 1 < cnt; i += 2) {
        int r0 = g_list[off + i], r1 = g_list[off + i + 1];
        float4 a = *reinterpret_cast<const float4*>(&g_nn[(size_t)r0 * DDIM + tid * 4]);
        float4 b = *reinterpret_cast<const float4*>(&g_nn[(size_t)r1 * DDIM + tid * 4]);
        acc.x += a.x + b.x; acc.y += a.y + b.y; acc.z += a.z + b.z; acc.w += a.w + b.w;
    }
    if (i < cnt) {
        int r0 = g_list[off + i];
        float4 a = *reinterpret_cast<const float4*>(&g_nn[(size_t)r0 * DDIM + tid * 4]);
        acc.x += a.x; acc.y += a.y; acc.z += a.z; acc.w += a.w;
    }
    const float* dsrc = (c < NGD) ? (gd + (size_t)c * DDIM) : (ld + (size_t)(c - NGD) * DDIM);
    const float m = (c < NGD) ? 0.999f : 0.8f;
    float4 d = *reinterpret_cast<const float4*>(&dsrc[tid * 4]);
    float u0, u1, u2, u3;
    if (cnt > 0) {
        float w = (1.f - m) / (float)cnt;
        u0 = m * d.x + w * acc.x; u1 = m * d.y + w * acc.y;
        u2 = m * d.z + w * acc.z; u3 = m * d.w + w * acc.w;
    } else { u0 = d.x; u1 = d.y; u2 = d.z; u3 = d.w; }
    float ss = u0 * u0 + u1 * u1 + u2 * u2 + u3 * u3;
#pragma unroll
    for (int off2 = 16; off2; off2 >>= 1) ss += __shfl_down_sync(0xffffffffu, ss, off2);
    if ((tid & 31) == 0) red[tid >> 5] = ss;
    __syncthreads();
    if (tid == 0) {
        float s = 0.f;
#pragma unroll
        for (int j = 0; j < 8; j++) s += red[j];
        red[0] = s;
    }
    __syncthreads();
    float inv = 1.f / fmaxf(sqrtf(red[0]), 1e-12f);
    float f[4] = {u0 * inv, u1 * inv, u2 * inv, u3 * inv};
    size_t o = (size_t)c * DDIM + tid * 4;
    *reinterpret_cast<float4*>(&g_comb[o]) = make_float4(f[0], f[1], f[2], f[3]);
    bf h[4], l[4];
#pragma unroll
    for (int j = 0; j < 4; j++) split2(f[j], h[j], l[j]);
    *reinterpret_cast<uint2*>(&ch[o]) = *reinterpret_cast<uint2*>(h);
    *reinterpret_cast<uint2*>(&cl[o]) = *reinterpret_cast<uint2*>(l);
}

// ---------------- softmax ----------------------------------------------------
__global__ __launch_bounds__(256)
void softmax_split_kernel(const float* __restrict__ S, bf* __restrict__ Wh,
                          bf* __restrict__ Wl) {
    __shared__ float red[8];
    const int r = blockIdx.x, tid = threadIdx.x;
    const float* s = S + (size_t)r * NCOMB;
    float v[5];
#pragma unroll
    for (int i = 0; i < 5; i++) v[i] = s[tid + i * 256];
    float mx = v[0];
#pragma unroll
    for (int i = 1; i < 5; i++) mx = fmaxf(mx, v[i]);
#pragma unroll
    for (int off = 16; off; off >>= 1) mx = fmaxf(mx, __shfl_down_sync(0xffffffffu, mx, off));
    if ((tid & 31) == 0) red[tid >> 5] = mx;
    __syncthreads();
    if (tid == 0) {
        float t = red[0];
#pragma unroll
        for (int i = 1; i < 8; i++) t = fmaxf(t, red[i]);
        red[0] = t;
    }
    __syncthreads();
    mx = red[0];
    __syncthreads();
    float ssum = 0.f;
#pragma unroll
    for (int i = 0; i < 5; i++) { v[i] = expf((v[i] - mx) * (1.f / 0.07f)); ssum += v[i]; }
#pragma unroll
    for (int off = 16; off; off >>= 1) ssum += __shfl_down_sync(0xffffffffu, ssum, off);
    if ((tid & 31) == 0) red[tid >> 5] = ssum;
    __syncthreads();
    if (tid == 0) {
        float t = 0.f;
#pragma unroll
        for (int i = 0; i < 8; i++) t += red[i];
        red[0] = t;
    }
    __syncthreads();
    float inv = 1.f / red[0];
#pragma unroll
    for (int i = 0; i < 5; i++) {
        bf h, l;
        split2(v[i] * inv, h, l);
        Wh[(size_t)r * NCOMB + tid + i * 256] = h;
        Wl[(size_t)r * NCOMB + tid + i * 256] = l;
    }
}

__global__ void finalize_kernel(float* out_loss) {
    *out_loss = (float)(g_acc[0] / ((double)NROWS * (double)NGD) +
                        g_acc[1] / ((double)NROWS * (double)NLD) +
                        g_acc[2] / (double)NROWS);
}

// ---------------- launch ----------------------------------------------------
extern "C" void kernel_launch(void* const* d_in, const int* in_sizes, int n_in,
                              void* d_out, int out_size) {
    const float* z  = (const float*)d_in[0];
    const float* u  = (const float*)d_in[1];
    const float* W1 = (const float*)d_in[2];
    const float* b1 = (const float*)d_in[3];
    const float* W2 = (const float*)d_in[4];
    const float* b2 = (const float*)d_in[5];
    const float* Wg = (const float*)d_in[6];
    const float* bg = (const float*)d_in[7];
    const float* gd = (const float*)d_in[8];
    const float* ld = (const float*)d_in[9];

    float* out       = (float*)d_out;
    float* out_zc    = out;
    float* out_loss  = out + (size_t)NROWS * DDIM;
    float* out_zproj = out_loss + 1;
    float* out_u     = out_zproj + (size_t)NROWS * DDIM;

    static float *p_zp = nullptr, *p_nn, *p_gate, *p_S, *p_comb;
    static int* p_idx;
    static bf *zb, *hb, *zpb, *nnb, *znb, *Sb, *W1T, *W2T, *WgT, *gdb, *ldb, *cbb, *ctb;
    static size_t szNM, szNS, szDD, szGD, szLD, szCB;
    if (!p_zp) {
        cudaGetSymbolAddress((void**)&p_zp, g_zp);
        cudaGetSymbolAddress((void**)&p_nn, g_nn);
        cudaGetSymbolAddress((void**)&p_gate, g_gate);
        cudaGetSymbolAddress((void**)&p_S, g_S);
        cudaGetSymbolAddress((void**)&p_comb, g_comb);
        cudaGetSymbolAddress((void**)&p_idx, g_idx);
        cudaGetSymbolAddress((void**)&zb, b_z);
        cudaGetSymbolAddress((void**)&hb, b_h);
        cudaGetSymbolAddress((void**)&zpb, b_zp);
        cudaGetSymbolAddress((void**)&nnb, b_nn);
        cudaGetSymbolAddress((void**)&znb, b_zn);
        cudaGetSymbolAddress((void**)&Sb, b_S);
        cudaGetSymbolAddress((void**)&W1T, b_W1T);
        cudaGetSymbolAddress((void**)&W2T, b_W2T);
        cudaGetSymbolAddress((void**)&WgT, b_WgT);
        cudaGetSymbolAddress((void**)&gdb, b_gd);
        cudaGetSymbolAddress((void**)&ldb, b_ld);
        cudaGetSymbolAddress((void**)&cbb, b_comb);
        cudaGetSymbolAddress((void**)&ctb, b_combT);
        szNM = NM; szNS = (size_t)NROWS * NCOMB; szDD = DDIM * DDIM;
        szGD = NGD * DDIM; szLD = NLD * DDIM; szCB = NCOMB * DDIM;
        cudaFuncSetAttribute(gemm_mma<EPI_RELU_BIAS, 3, false, true, false>,
                             cudaFuncAttributeMaxDynamicSharedMemorySize, SM_TOTAL);
        cudaFuncSetAttribute(gemm_mma<EPI_BIAS, 3, true, true, true>,
                             cudaFuncAttributeMaxDynamicSharedMemorySize, SM_TOTAL);
        cudaFuncSetAttribute(gemm_mma<EPI_SIGMOID, 1, true, false, false>,
                             cudaFuncAttributeMaxDynamicSharedMemorySize, SM_TOTAL);
        cudaFuncSetAttribute(gemm_mma<EPI_S_LOSS, 2, true, false, false>,
                             cudaFuncAttributeMaxDynamicSharedMemorySize, SM_TOTAL);
        cudaFuncSetAttribute(gemm_mma<EPI_ZCLEAN, 1, true, false, false>,
                             cudaFuncAttributeMaxDynamicSharedMemorySize, SM_TOTAL);
        cudaFuncSetAttribute(argmax_dual,
                             cudaFuncAttributeMaxDynamicSharedMemorySize, SM_TOTAL);
    }

    const dim3 gD(DDIM / 128, NROWS / 128);

    // [0] init
    init_kernel<<<5, 256>>>();
    // [1] convert z
    conv_split_kernel<<<NM / 1024, 256>>>(z, zb, zb + szNM, NM);
    // [2] W1^T
    transconv_kernel<<<dim3(DDIM / 32, DDIM / 32), 256>>>(W1, DDIM, DDIM, W1T, W1T + szDD);
    // [3] proj1 GEMM (NPROD=3)  <-- ncu capture window target
    gemm_mma<EPI_RELU_BIAS, 3, false, true, false><<<gD, 128, SM_TOTAL>>>(
        zb, zb + szNM, W1T, W1T + szDD, b1, nullptr, hb, hb + szNM, nullptr, DDIM, DDIM,
        nullptr, nullptr);
    // [4..7] remaining conversions
    conv_split_kernel<<<(NGD * DDIM) / 1024, 256>>>(gd, gdb, gdb + szGD, NGD * DDIM);
    conv_split_kernel<<<(NLD * DDIM) / 1024, 256>>>(ld, ldb, ldb + szLD, NLD * DDIM);
    transconv_kernel<<<dim3(DDIM / 32, DDIM / 32), 256>>>(W2, DDIM, DDIM, W2T, W2T + szDD);
    transconv_kernel<<<dim3(DDIM / 32, DDIM / 32), 256>>>(Wg, DDIM, DDIM, WgT, WgT + szDD);
    // [8] noise_norm + fused raw-u copy (fp32 nn kept: dictupd gathers from it)
    rownorm_split_kernel<<<NROWS, 256>>>(u, p_nn, nnb, nnb + szNM, out_u, nullptr);
    // [9] proj2 (NPROD=3)
    gemm_mma<EPI_BIAS, 3, true, true, true><<<gD, 128, SM_TOTAL>>>(
        hb, hb + szNM, W2T, W2T + szDD, b2, p_zp, zpb, zpb + szNM, out_zproj, DDIM, DDIM,
        nullptr, nullptr);
    // [10] z_norm (bf split only; fp32 z_norm has no consumer) + fused loss_direct
    rownorm_split_kernel<<<NROWS, 256>>>(p_zp, nullptr, znb, znb + szNM, nullptr, p_nn);
    // [11] gate (NPROD=1)
    gemm_mma<EPI_SIGMOID, 1, true, false, false><<<gD, 128, SM_TOTAL>>>(
        zpb, zpb + szNM, WgT, WgT + szDD, bg, p_gate, nullptr, nullptr, nullptr, DDIM, DDIM,
        nullptr, nullptr);
    // [12] dual argmax + counts (NPROD=2: sims err ~6e-5, flips only on <1e-4 gaps)
    argmax_dual<<<NROWS / 128, 128, SM_TOTAL>>>(nnb, nnb + szNM,
                                                gdb, gdb + szGD, ldb, ldb + szLD, p_idx);
    // [13..15] scan / fill lists / gather dict update
    scan_kernel<<<1, 256>>>();
    fill_list_kernel<<<NROWS / 256, 256>>>(p_idx);
    dictupd_kernel<<<NCOMB, 256>>>(gd, ld, cbb, cbb + szCB);
    // [16] S = z_norm @ comb^T (NPROD=2; + fused sum|S|)
    gemm_mma<EPI_S_LOSS, 2, true, false, false><<<dim3(NCOMB / 128, NROWS / 128), 128, SM_TOTAL>>>(
        znb, znb + szNM, cbb, cbb + szCB, nullptr, p_S, nullptr, nullptr, nullptr, NCOMB, DDIM,
        nullptr, nullptr);
    // [17..18] softmax + comb^T
    softmax_split_kernel<<<NROWS, 256>>>(p_S, Sb, Sb + szNS);
    transconv_kernel<<<dim3(DDIM / 32, NCOMB / 32), 256>>>(p_comb, NCOMB, DDIM, ctb, ctb + szCB);
    // [19] weighted_u + fused z_clean (NPROD=1)
    gemm_mma<EPI_ZCLEAN, 1, true, false, false><<<gD, 128, SM_TOTAL>>>(
        Sb, Sb + szNS, ctb, ctb + szCB, nullptr, out_zc, nullptr, nullptr, nullptr, DDIM, NCOMB,
        z, p_gate);
    // [20] finalize loss
    finalize_kernel<<<1, 1>>>(out_loss);
}

// round 17
// speedup vs baseline: 1.5004x; 1.5004x over previous
#include <cuda_runtime.h>
#include <cuda_bf16.h>
#include <math.h>
#include <stdint.h>

#define NROWS 32768
#define DDIM  1024
#define NGD   1024
#define NLD   256
#define NCOMB 1280
#define NM    (NROWS * DDIM)

typedef __nv_bfloat16 bf;

// ---------------- warp MMA primitives (plain sm_80+ PTX, no 'a' features) --
__device__ __forceinline__ uint32_t smem_u32(const void* p) {
    uint32_t a;
    asm("{ .reg .u64 t; cvta.to.shared.u64 t, %1; cvt.u32.u64 %0, t; }" : "=r"(a) : "l"(p));
    return a;
}
__device__ __forceinline__ void ldsm4(uint32_t addr, uint32_t* f) {
    asm volatile("ldmatrix.sync.aligned.m8n8.x4.shared.b16 {%0,%1,%2,%3}, [%4];"
                 : "=r"(f[0]), "=r"(f[1]), "=r"(f[2]), "=r"(f[3]) : "r"(addr));
}
__device__ __forceinline__ void mma16816(float* c, const uint32_t* a, uint32_t b0, uint32_t b1) {
    asm volatile("mma.sync.aligned.m16n8k16.row.col.f32.bf16.bf16.f32 "
                 "{%0,%1,%2,%3}, {%4,%5,%6,%7}, {%8,%9}, {%0,%1,%2,%3};"
                 : "+f"(c[0]), "+f"(c[1]), "+f"(c[2]), "+f"(c[3])
                 : "r"(a[0]), "r"(a[1]), "r"(a[2]), "r"(a[3]), "r"(b0), "r"(b1));
}
__device__ __forceinline__ void cp16(uint32_t dst, const void* src) {
    asm volatile("cp.async.cg.shared.global [%0], [%1], 16;" :: "r"(dst), "l"(src));
}
#define CP_COMMIT() asm volatile("cp.async.commit_group;" ::: "memory")
#define CP_WAIT(n)  asm volatile("cp.async.wait_group %0;" :: "n"(n) : "memory")

__device__ __forceinline__ void split2(float x, bf& h, bf& l) {
    h = __float2bfloat16(x);
    l = __float2bfloat16(x - __bfloat162float(h));
}

// ---------------- scratch ---------------------------------------------------
__device__ float  g_zp[NM];
__device__ float  g_nn[NM];
__device__ float  g_gate[NM];
__device__ float  g_S[(size_t)NROWS * NCOMB];
__device__ float  g_comb[NCOMB * DDIM];
__device__ float  g_cnts[NCOMB];
__device__ int    g_cnt_i[NCOMB];
__device__ int    g_cur[NCOMB];
__device__ int    g_off[NCOMB];
__device__ int    g_list[2 * NROWS];
__device__ int    g_idx[2 * NROWS];
__device__ double g_acc[3];

__device__ bf b_z[2][NM];
__device__ bf b_h[2][NM];
__device__ bf b_zp[2][NM];
__device__ bf b_nn[2][NM];
__device__ bf b_zn[2][NM];
__device__ bf b_S[2][(size_t)NROWS * NCOMB];
__device__ bf b_W1T[2][DDIM * DDIM];
__device__ bf b_W2T[2][DDIM * DDIM];
__device__ bf b_WgT[2][DDIM * DDIM];
__device__ bf b_gd[2][NGD * DDIM];
__device__ bf b_ld[2][NLD * DDIM];
__device__ bf b_comb[2][NCOMB * DDIM];
__device__ bf b_combT[2][DDIM * NCOMB];

// ---------------- small kernels --------------------------------------------
__global__ void init_kernel() {
    int i = blockIdx.x * blockDim.x + threadIdx.x;
    if (i < NCOMB) { g_cnt_i[i] = 0; g_cur[i] = 0; }
    if (i < 3)     g_acc[i] = 0.0;
}

__global__ __launch_bounds__(256)
void conv_split_kernel(const float* __restrict__ src, bf* __restrict__ dh,
                       bf* __restrict__ dl, int n) {
    int i = (blockIdx.x * blockDim.x + threadIdx.x) * 4;
    if (i + 3 < n) {
        float4 v = *reinterpret_cast<const float4*>(&src[i]);
        bf h[4], l[4];
        split2(v.x, h[0], l[0]); split2(v.y, h[1], l[1]);
        split2(v.z, h[2], l[2]); split2(v.w, h[3], l[3]);
        *reinterpret_cast<uint2*>(&dh[i]) = *reinterpret_cast<uint2*>(h);
        *reinterpret_cast<uint2*>(&dl[i]) = *reinterpret_cast<uint2*>(l);
    }
}

// tiled transpose + split: src [R][C] fp32 -> dst [c][r] bf16 hi/lo
__global__ __launch_bounds__(256)
void transconv_kernel(const float* __restrict__ src, int R, int C,
                      bf* __restrict__ dh, bf* __restrict__ dl) {
    __shared__ float t[32][33];
    const int bx = blockIdx.x * 32, by = blockIdx.y * 32;
    const int tx = threadIdx.x & 31, ty = threadIdx.x >> 5;
#pragma unroll
    for (int i = 0; i < 4; i++)
        t[ty + 8 * i][tx] = src[(size_t)(by + ty + 8 * i) * C + bx + tx];
    __syncthreads();
#pragma unroll
    for (int i = 0; i < 4; i++) {
        float x = t[tx][ty + 8 * i];
        bf h, l; split2(x, h, l);
        size_t o = (size_t)(bx + ty + 8 * i) * R + by + tx;
        dh[o] = h; dl[o] = l;
    }
}

// row L2 normalize; optional fp32 out; bf16 hi/lo; optional raw copy; optional
// fused |dot(normalized, UN_row)| accumulation into g_acc[2]
__global__ __launch_bounds__(256)
void rownorm_split_kernel(const float* __restrict__ X, float* __restrict__ Y,
                          bf* __restrict__ Yh, bf* __restrict__ Yl,
                          float* __restrict__ Cpy, const float* __restrict__ UN) {
    __shared__ float red[8];
    const int r = blockIdx.x, tid = threadIdx.x;
    float4 x = *reinterpret_cast<const float4*>(&X[(size_t)r * DDIM + tid * 4]);
    float ss = x.x * x.x + x.y * x.y + x.z * x.z + x.w * x.w;
#pragma unroll
    for (int off = 16; off; off >>= 1) ss += __shfl_down_sync(0xffffffffu, ss, off);
    if ((tid & 31) == 0) red[tid >> 5] = ss;
    __syncthreads();
    if (tid == 0) {
        float s = 0.f;
#pragma unroll
        for (int i = 0; i < 8; i++) s += red[i];
        red[0] = s;
    }
    __syncthreads();
    float inv = 1.f / fmaxf(sqrtf(red[0]), 1e-12f);
    float f[4] = {x.x * inv, x.y * inv, x.z * inv, x.w * inv};
    size_t o = (size_t)r * DDIM + tid * 4;
    if (Y) *reinterpret_cast<float4*>(&Y[o]) = make_float4(f[0], f[1], f[2], f[3]);
    bf h[4], l[4];
#pragma unroll
    for (int i = 0; i < 4; i++) split2(f[i], h[i], l[i]);
    *reinterpret_cast<uint2*>(&Yh[o]) = *reinterpret_cast<uint2*>(h);
    *reinterpret_cast<uint2*>(&Yl[o]) = *reinterpret_cast<uint2*>(l);
    if (Cpy) { Cpy[o] = x.x; Cpy[o + 1] = x.y; Cpy[o + 2] = x.z; Cpy[o + 3] = x.w; }
    if (UN) {
        float4 un = *reinterpret_cast<const float4*>(&UN[o]);
        float p = f[0] * un.x + f[1] * un.y + f[2] * un.z + f[3] * un.w;
#pragma unroll
        for (int off = 16; off; off >>= 1) p += __shfl_down_sync(0xffffffffu, p, off);
        __syncthreads();
        if ((tid & 31) == 0) red[tid >> 5] = p;
        __syncthreads();
        if (tid == 0) {
            float s = 0.f;
#pragma unroll
            for (int i = 0; i < 8; i++) s += red[i];
            atomicAdd(&g_acc[2], (double)fabsf(s));
        }
    }
}

// ---------------- HMMA GEMM (3-stage cp.async, XOR swizzle, 4 warps @64x64) --
// NPROD: 1 = ah*bh, 2 = (ah+al)*bh, 3 = full hi/lo split
enum { EPI_RELU_BIAS = 0, EPI_BIAS = 1, EPI_SIGMOID = 2, EPI_S_LOSS = 3, EPI_ZCLEAN = 4 };

#define TILE_B  8192                 // 128 rows x 64 bytes (32 bf16), swizzled
#define STAGE_B (4 * TILE_B)         // 32768 per stage (slots: Ah, Al, Bh, Bl)
#define SM_TOTAL (3 * STAGE_B)       // 98304 : 2 CTAs/SM

// swizzled byte offset inside a tile: row in [0,128), c16 in [0,4)
__device__ __forceinline__ uint32_t swz(int row, int c16) {
    return (uint32_t)(row * 64 + ((c16 ^ ((row >> 1) & 3)) << 4));
}

// cp.async fill of one 32-wide K-chunk into stage s; loads only tiles NPROD needs
template <int NPROD>
__device__ __forceinline__ void fill_async(
    uint32_t sb, int s,
    const bf* __restrict__ Ah, const bf* __restrict__ Al,
    const bf* __restrict__ Bh, const bf* __restrict__ Bl,
    int m0, int n0, int k0, int K, int tid) {
    const uint32_t base = sb + s * STAGE_B;
#pragma unroll
    for (int t = 0; t < 4; t++) {
        if (t == 1 && NPROD < 2) continue;   // Al unused
        if (t == 3 && NPROD < 3) continue;   // Bl unused
        const bf* gp = (t == 0) ? Ah : (t == 1) ? Al : (t == 2) ? Bh : Bl;
        const int rb = (t < 2) ? m0 : n0;
        const uint32_t tb = base + t * TILE_B;
#pragma unroll
        for (int v = 0; v < 4; v++) {
            int idx = v * 128 + tid;
            int row = idx >> 2, c16 = idx & 3;
            cp16(tb + swz(row, c16), gp + (size_t)(rb + row) * K + k0 + c16 * 8);
        }
    }
    CP_COMMIT();
}

// NPROD-tiered compute of one K-chunk into acc[4][8][4] (warp 64x64)
template <int NPROD>
__device__ __forceinline__ void chunk_mma(float acc[4][8][4], uint32_t base,
                                          int lane, int warp_m, int warp_n) {
    const int arow = warp_m + (lane & 15);
    const int ahi  = lane >> 4;
    const int brow = warp_n + ((lane & 7) | ((lane >> 4) << 3));
    const int bhi  = (lane >> 3) & 1;
#pragma unroll
    for (int ks = 0; ks < 2; ks++) {
        uint32_t bh[16], bl[16];
#pragma unroll
        for (int i = 0; i < 4; i++) {
            uint32_t off = swz(brow + i * 16, ks * 2 + bhi);
            ldsm4(base + 2 * TILE_B + off, bh + 4 * i);
            if (NPROD >= 3) ldsm4(base + 3 * TILE_B + off, bl + 4 * i);
        }
#pragma unroll
        for (int mt = 0; mt < 4; mt++) {
            uint32_t off = swz(arow + mt * 16, ks * 2 + ahi);
            uint32_t ah[4], al[4];
            ldsm4(base + off, ah);
            if (NPROD >= 2) ldsm4(base + TILE_B + off, al);
#pragma unroll
            for (int nt = 0; nt < 8; nt++) {
                mma16816(acc[mt][nt], ah, bh[2 * nt], bh[2 * nt + 1]);
                if (NPROD >= 3) mma16816(acc[mt][nt], ah, bl[2 * nt], bl[2 * nt + 1]);
                if (NPROD >= 2) mma16816(acc[mt][nt], al, bh[2 * nt], bh[2 * nt + 1]);
            }
        }
    }
}

// 3-stage mainloop: one __syncthreads per chunk.
#define GEMM_MAINLOOP(NP, Ahp, Alp, Bhp, Blp, M0, N0, KK)                               \
    do {                                                                                \
        const int nch = (KK) >> 5;                                                      \
        fill_async<NP>(sb, 0, Ahp, Alp, Bhp, Blp, M0, N0, 0, KK, tid);                  \
        fill_async<NP>(sb, 1, Ahp, Alp, Bhp, Blp, M0, N0, 32, KK, tid);                 \
        for (int kc = 0; kc < nch; kc++) {                                              \
            if (kc + 1 < nch) { CP_WAIT(1); } else { CP_WAIT(0); }                      \
            __syncthreads();                                                            \
            if (kc + 2 < nch)                                                           \
                fill_async<NP>(sb, (kc + 2) % 3, Ahp, Alp, Bhp, Blp, M0, N0,            \
                               (kc + 2) << 5, KK, tid);                                 \
            chunk_mma<NP>(acc, sb + (kc % 3) * STAGE_B, lane, warp_m, warp_n);          \
        }                                                                               \
    } while (0)

template <int EPI, int NPROD, bool WF32, bool WSPLIT, bool WMIS>
__global__ __launch_bounds__(128)
void gemm_mma(const bf* __restrict__ Ah, const bf* __restrict__ Al,
              const bf* __restrict__ Bh, const bf* __restrict__ Bl,
              const float* __restrict__ bias, float* __restrict__ Cf,
              bf* __restrict__ Ch, bf* __restrict__ Cl, float* __restrict__ Cm,
              int Ncols, int K,
              const float* __restrict__ e1, const float* __restrict__ e2) {
    extern __shared__ __align__(16) char smem[];
    const uint32_t sb = smem_u32(smem);
    const int tid = threadIdx.x, lane = tid & 31, wid = tid >> 5;
    const int m0 = blockIdx.y * 128, n0 = blockIdx.x * 128;
    const int warp_m = (wid >> 1) * 64, warp_n = (wid & 1) * 64;

    float acc[4][8][4] = {};
    GEMM_MAINLOOP(NPROD, Ah, Al, Bh, Bl, m0, n0, K);

    // ---------------- epilogue ----------------
    double part = 0.0;
#pragma unroll
    for (int mt = 0; mt < 4; mt++) {
        const int r0 = m0 + warp_m + mt * 16 + (lane >> 2);
#pragma unroll
        for (int nt = 0; nt < 8; nt++) {
            const int col = n0 + warp_n + nt * 8 + ((lane & 3) << 1);
            float b2x = 0.f, b2y = 0.f;
            if (EPI == EPI_RELU_BIAS || EPI == EPI_BIAS || EPI == EPI_SIGMOID) {
                float2 bb = *reinterpret_cast<const float2*>(bias + col);
                b2x = bb.x; b2y = bb.y;
            }
#pragma unroll
            for (int h = 0; h < 2; h++) {
                const int row = r0 + h * 8;
                float v0 = acc[mt][nt][2 * h], v1 = acc[mt][nt][2 * h + 1];
                if (EPI == EPI_RELU_BIAS) { v0 = fmaxf(v0 + b2x, 0.f); v1 = fmaxf(v1 + b2y, 0.f); }
                else if (EPI == EPI_BIAS) { v0 += b2x; v1 += b2y; }
                else if (EPI == EPI_SIGMOID) {
                    v0 = 1.f / (1.f + expf(-(v0 + b2x)));
                    v1 = 1.f / (1.f + expf(-(v1 + b2y)));
                }
                const size_t ro = (size_t)row * Ncols + col;
                if (EPI == EPI_ZCLEAN) {
                    float2 z2 = *reinterpret_cast<const float2*>(e1 + ro);
                    float2 q2 = *reinterpret_cast<const float2*>(e2 + ro);
                    v0 = z2.x - q2.x * v0;
                    v1 = z2.y - q2.y * v1;
                }
                if (EPI == EPI_S_LOSS) part += (double)fabsf(v0) + (double)fabsf(v1);
                if (WF32)
                    *reinterpret_cast<float2*>(Cf + ro) = make_float2(v0, v1);
                if (WMIS) { Cm[ro] = v0; Cm[ro + 1] = v1; }
                if (WSPLIT) {
                    bf h0, l0, h1, l1;
                    split2(v0, h0, l0); split2(v1, h1, l1);
                    bf hp[2] = {h0, h1}, lp[2] = {l0, l1};
                    *reinterpret_cast<uint32_t*>(Ch + ro) = *reinterpret_cast<uint32_t*>(hp);
                    *reinterpret_cast<uint32_t*>(Cl + ro) = *reinterpret_cast<uint32_t*>(lp);
                }
            }
        }
    }
    if (EPI == EPI_S_LOSS) {
#pragma unroll
        for (int off = 16; off; off >>= 1) part += __shfl_down_sync(0xffffffffu, part, off);
        if (lane == 0) atomicAdd(&g_acc[(n0 < NGD) ? 0 : 1], part);
    }
}

// ---------------- dual-dict HMMA argmax + count (NPROD=2) --------------------
__global__ __launch_bounds__(128)
void argmax_dual(const bf* __restrict__ Ah, const bf* __restrict__ Al,
                 const bf* __restrict__ Gh, const bf* __restrict__ Gl,
                 const bf* __restrict__ Lh, const bf* __restrict__ Ll,
                 int* __restrict__ idx_out) {
    extern __shared__ __align__(16) char smem[];
    __shared__ float sval[128][2];
    __shared__ int   sidx[128][2];
    const uint32_t sb = smem_u32(smem);
    const int tid = threadIdx.x, lane = tid & 31, wid = tid >> 5;
    const int m0 = blockIdx.x * 128;
    const int warp_m = (wid >> 1) * 64, warp_n = (wid & 1) * 64;

    for (int part = 0; part < 2; part++) {
        const bf* Dh = part ? Lh : Gh;
        const bf* Dl = part ? Ll : Gl;
        const int ncodes = part ? NLD : NGD;

        float bv[8]; int bi[8];
#pragma unroll
        for (int i = 0; i < 8; i++) { bv[i] = -1e30f; bi[i] = 0; }

        for (int n0 = 0; n0 < ncodes; n0 += 128) {
            float acc[4][8][4] = {};
            GEMM_MAINLOOP(2, Ah, Al, Dh, Dl, m0, n0, DDIM);
            __syncthreads();  // reads done before next tile's preload overwrites
#pragma unroll
            for (int mt = 0; mt < 4; mt++)
#pragma unroll
                for (int h = 0; h < 2; h++) {
                    float* bvp = &bv[mt * 2 + h]; int* bip = &bi[mt * 2 + h];
#pragma unroll
                    for (int nt = 0; nt < 8; nt++) {
                        const int col = n0 + warp_n + nt * 8 + ((lane & 3) << 1);
                        float v0 = acc[mt][nt][2 * h], v1 = acc[mt][nt][2 * h + 1];
                        if (v0 > *bvp) { *bvp = v0; *bip = col; }
                        if (v1 > *bvp) { *bvp = v1; *bip = col + 1; }
                    }
                }
        }
#pragma unroll
        for (int i = 0; i < 8; i++) {
            float v = bv[i]; int c = bi[i];
#pragma unroll
            for (int off = 1; off <= 2; off <<= 1) {
                float ov = __shfl_xor_sync(0xffffffffu, v, off);
                int   oc = __shfl_xor_sync(0xffffffffu, c, off);
                if (ov > v || (ov == v && oc < c)) { v = ov; c = oc; }
            }
            if ((lane & 3) == 0) {
                int row = warp_m + (i >> 1) * 16 + (i & 1) * 8 + (lane >> 2);
                sval[row][wid & 1] = v;
                sidx[row][wid & 1] = c;
            }
        }
        __syncthreads();
        {
            float v = sval[tid][0]; int c = sidx[tid][0];
            float ov = sval[tid][1]; int oc = sidx[tid][1];
            if (ov > v || (ov == v && oc < c)) { v = ov; c = oc; }
            idx_out[part * NROWS + m0 + tid] = c;
            atomicAdd(&g_cnt_i[part ? NGD + c : c], 1);
        }
        __syncthreads();
    }
}

// ---------------- scan / fill / gather dict update --------------------------
__global__ __launch_bounds__(256)
void scan_kernel() {
    __shared__ int ws[8];
    const int tid = threadIdx.x, lane = tid & 31, wid = tid >> 5;
    int v[5]; int s = 0;
#pragma unroll
    for (int i = 0; i < 5; i++) { v[i] = g_cnt_i[tid * 5 + i]; s += v[i]; }
    int x = s;
#pragma unroll
    for (int off = 1; off < 32; off <<= 1) {
        int t = __shfl_up_sync(0xffffffffu, x, off);
        if (lane >= off) x += t;
    }
    if (lane == 31) ws[wid] = x;
    __syncthreads();
    if (tid == 0) {
        int a = 0;
#pragma unroll
        for (int w = 0; w < 8; w++) { int t = ws[w]; ws[w] = a; a += t; }
    }
    __syncthreads();
    int run = x - s + ws[wid];
#pragma unroll
    for (int i = 0; i < 5; i++) {
        g_off[tid * 5 + i] = run;
        g_cnts[tid * 5 + i] = (float)v[i];
        run += v[i];
    }
}

__global__ __launch_bounds__(256)
void fill_list_kernel(const int* __restrict__ idx) {
    const int r = blockIdx.x * blockDim.x + threadIdx.x;
    if (r < NROWS) {
        int ig = idx[r];
        int pos = atomicAdd(&g_cur[ig], 1);
        g_list[g_off[ig] + pos] = r;
        int il = NGD + idx[NROWS + r];
        int pos2 = atomicAdd(&g_cur[il], 1);
        g_list[g_off[il] + pos2] = r;
    }
}

__global__ __launch_bounds__(256)
void dictupd_kernel(const float* __restrict__ gd, const float* __restrict__ ld,
                    bf* __restrict__ ch, bf* __restrict__ cl) {
    __shared__ float red[8];
    const int c = blockIdx.x, tid = threadIdx.x;
    const int cnt = g_cnt_i[c], off = g_off[c];
    float4 acc = make_float4(0.f, 0.f, 0.f, 0.f);
    int i = 0;
    for (; i + 1 < cnt; i += 2) {
        int r0 = g_list[off + i], r1 = g_list[off + i + 1];
        float4 a = *reinterpret_cast<const float4*>(&g_nn[(size_t)r0 * DDIM + tid * 4]);
        float4 b = *reinterpret_cast<const float4*>(&g_nn[(size_t)r1 * DDIM + tid * 4]);
        acc.x += a.x + b.x; acc.y += a.y + b.y; acc.z += a.z + b.z; acc.w += a.w + b.w;
    }
    if (i < cnt) {
        int r0 = g_list[off + i];
        float4 a = *reinterpret_cast<const float4*>(&g_nn[(size_t)r0 * DDIM + tid * 4]);
        acc.x += a.x; acc.y += a.y; acc.z += a.z; acc.w += a.w;
    }
    const float* dsrc = (c < NGD) ? (gd + (size_t)c * DDIM) : (ld + (size_t)(c - NGD) * DDIM);
    const float m = (c < NGD) ? 0.999f : 0.8f;
    float4 d = *reinterpret_cast<const float4*>(&dsrc[tid * 4]);
    float u0, u1, u2, u3;
    if (cnt > 0) {
        float w = (1.f - m) / (float)cnt;
        u0 = m * d.x + w * acc.x; u1 = m * d.y + w * acc.y;
        u2 = m * d.z + w * acc.z; u3 = m * d.w + w * acc.w;
    } else { u0 = d.x; u1 = d.y; u2 = d.z; u3 = d.w; }
    float ss = u0 * u0 + u1 * u1 + u2 * u2 + u3 * u3;
#pragma unroll
    for (int off2 = 16; off2; off2 >>= 1) ss += __shfl_down_sync(0xffffffffu, ss, off2);
    if ((tid & 31) == 0) red[tid >> 5] = ss;
    __syncthreads();
    if (tid == 0) {
        float s = 0.f;
#pragma unroll
        for (int j = 0; j < 8; j++) s += red[j];
        red[0] = s;
    }
    __syncthreads();
    float inv = 1.f / fmaxf(sqrtf(red[0]), 1e-12f);
    float f[4] = {u0 * inv, u1 * inv, u2 * inv, u3 * inv};
    size_t o = (size_t)c * DDIM + tid * 4;
    *reinterpret_cast<float4*>(&g_comb[o]) = make_float4(f[0], f[1], f[2], f[3]);
    bf h[4], l[4];
#pragma unroll
    for (int j = 0; j < 4; j++) split2(f[j], h[j], l[j]);
    *reinterpret_cast<uint2*>(&ch[o]) = *reinterpret_cast<uint2*>(h);
    *reinterpret_cast<uint2*>(&cl[o]) = *reinterpret_cast<uint2*>(l);
}

// ---------------- softmax ----------------------------------------------------
__global__ __launch_bounds__(256)
void softmax_split_kernel(const float* __restrict__ S, bf* __restrict__ Wh,
                          bf* __restrict__ Wl) {
    __shared__ float red[8];
    const int r = blockIdx.x, tid = threadIdx.x;
    const float* s = S + (size_t)r * NCOMB;
    float v[5];
#pragma unroll
    for (int i = 0; i < 5; i++) v[i] = s[tid + i * 256];
    float mx = v[0];
#pragma unroll
    for (int i = 1; i < 5; i++) mx = fmaxf(mx, v[i]);
#pragma unroll
    for (int off = 16; off; off >>= 1) mx = fmaxf(mx, __shfl_down_sync(0xffffffffu, mx, off));
    if ((tid & 31) == 0) red[tid >> 5] = mx;
    __syncthreads();
    if (tid == 0) {
        float t = red[0];
#pragma unroll
        for (int i = 1; i < 8; i++) t = fmaxf(t, red[i]);
        red[0] = t;
    }
    __syncthreads();
    mx = red[0];
    __syncthreads();
    float ssum = 0.f;
#pragma unroll
    for (int i = 0; i < 5; i++) { v[i] = expf((v[i] - mx) * (1.f / 0.07f)); ssum += v[i]; }
#pragma unroll
    for (int off = 16; off; off >>= 1) ssum += __shfl_down_sync(0xffffffffu, ssum, off);
    if ((tid & 31) == 0) red[tid >> 5] = ssum;
    __syncthreads();
    if (tid == 0) {
        float t = 0.f;
#pragma unroll
        for (int i = 0; i < 8; i++) t += red[i];
        red[0] = t;
    }
    __syncthreads();
    float inv = 1.f / red[0];
#pragma unroll
    for (int i = 0; i < 5; i++) {
        bf h, l;
        split2(v[i] * inv, h, l);
        Wh[(size_t)r * NCOMB + tid + i * 256] = h;
        Wl[(size_t)r * NCOMB + tid + i * 256] = l;
    }
}

__global__ void finalize_kernel(float* out_loss) {
    *out_loss = (float)(g_acc[0] / ((double)NROWS * (double)NGD) +
                        g_acc[1] / ((double)NROWS * (double)NLD) +
                        g_acc[2] / (double)NROWS);
}

// ---------------- launch ----------------------------------------------------
extern "C" void kernel_launch(void* const* d_in, const int* in_sizes, int n_in,
                              void* d_out, int out_size) {
    const float* z  = (const float*)d_in[0];
    const float* u  = (const float*)d_in[1];
    const float* W1 = (const float*)d_in[2];
    const float* b1 = (const float*)d_in[3];
    const float* W2 = (const float*)d_in[4];
    const float* b2 = (const float*)d_in[5];
    const float* Wg = (const float*)d_in[6];
    const float* bg = (const float*)d_in[7];
    const float* gd = (const float*)d_in[8];
    const float* ld = (const float*)d_in[9];

    float* out       = (float*)d_out;
    float* out_zc    = out;
    float* out_loss  = out + (size_t)NROWS * DDIM;
    float* out_zproj = out_loss + 1;
    float* out_u     = out_zproj + (size_t)NROWS * DDIM;

    static float *p_zp = nullptr, *p_nn, *p_gate, *p_S, *p_comb;
    static int* p_idx;
    static bf *zb, *hb, *zpb, *nnb, *znb, *Sb, *W1T, *W2T, *WgT, *gdb, *ldb, *cbb, *ctb;
    static size_t szNM, szNS, szDD, szGD, szLD, szCB;
    if (!p_zp) {
        cudaGetSymbolAddress((void**)&p_zp, g_zp);
        cudaGetSymbolAddress((void**)&p_nn, g_nn);
        cudaGetSymbolAddress((void**)&p_gate, g_gate);
        cudaGetSymbolAddress((void**)&p_S, g_S);
        cudaGetSymbolAddress((void**)&p_comb, g_comb);
        cudaGetSymbolAddress((void**)&p_idx, g_idx);
        cudaGetSymbolAddress((void**)&zb, b_z);
        cudaGetSymbolAddress((void**)&hb, b_h);
        cudaGetSymbolAddress((void**)&zpb, b_zp);
        cudaGetSymbolAddress((void**)&nnb, b_nn);
        cudaGetSymbolAddress((void**)&znb, b_zn);
        cudaGetSymbolAddress((void**)&Sb, b_S);
        cudaGetSymbolAddress((void**)&W1T, b_W1T);
        cudaGetSymbolAddress((void**)&W2T, b_W2T);
        cudaGetSymbolAddress((void**)&WgT, b_WgT);
        cudaGetSymbolAddress((void**)&gdb, b_gd);
        cudaGetSymbolAddress((void**)&ldb, b_ld);
        cudaGetSymbolAddress((void**)&cbb, b_comb);
        cudaGetSymbolAddress((void**)&ctb, b_combT);
        szNM = NM; szNS = (size_t)NROWS * NCOMB; szDD = DDIM * DDIM;
        szGD = NGD * DDIM; szLD = NLD * DDIM; szCB = NCOMB * DDIM;
        cudaFuncSetAttribute(gemm_mma<EPI_RELU_BIAS, 3, false, true, false>,
                             cudaFuncAttributeMaxDynamicSharedMemorySize, SM_TOTAL);
        cudaFuncSetAttribute(gemm_mma<EPI_BIAS, 3, true, true, true>,
                             cudaFuncAttributeMaxDynamicSharedMemorySize, SM_TOTAL);
        cudaFuncSetAttribute(gemm_mma<EPI_SIGMOID, 1, true, false, false>,
                             cudaFuncAttributeMaxDynamicSharedMemorySize, SM_TOTAL);
        cudaFuncSetAttribute(gemm_mma<EPI_S_LOSS, 2, true, false, false>,
                             cudaFuncAttributeMaxDynamicSharedMemorySize, SM_TOTAL);
        cudaFuncSetAttribute(gemm_mma<EPI_ZCLEAN, 1, true, false, false>,
                             cudaFuncAttributeMaxDynamicSharedMemorySize, SM_TOTAL);
        cudaFuncSetAttribute(argmax_dual,
                             cudaFuncAttributeMaxDynamicSharedMemorySize, SM_TOTAL);
    }

    const dim3 gD(DDIM / 128, NROWS / 128);

    // [0] init
    init_kernel<<<5, 256>>>();
    // [1] convert z
    conv_split_kernel<<<NM / 1024, 256>>>(z, zb, zb + szNM, NM);
    // [2] W1^T
    transconv_kernel<<<dim3(DDIM / 32, DDIM / 32), 256>>>(W1, DDIM, DDIM, W1T, W1T + szDD);
    // [3] proj1 GEMM (NPROD=3)  <-- ncu capture window target
    gemm_mma<EPI_RELU_BIAS, 3, false, true, false><<<gD, 128, SM_TOTAL>>>(
        zb, zb + szNM, W1T, W1T + szDD, b1, nullptr, hb, hb + szNM, nullptr, DDIM, DDIM,
        nullptr, nullptr);
    // [4..7] remaining conversions
    conv_split_kernel<<<(NGD * DDIM) / 1024, 256>>>(gd, gdb, gdb + szGD, NGD * DDIM);
    conv_split_kernel<<<(NLD * DDIM) / 1024, 256>>>(ld, ldb, ldb + szLD, NLD * DDIM);
    transconv_kernel<<<dim3(DDIM / 32, DDIM / 32), 256>>>(W2, DDIM, DDIM, W2T, W2T + szDD);
    transconv_kernel<<<dim3(DDIM / 32, DDIM / 32), 256>>>(Wg, DDIM, DDIM, WgT, WgT + szDD);
    // [8] noise_norm + fused raw-u copy (fp32 nn kept: dictupd gathers from it)
    rownorm_split_kernel<<<NROWS, 256>>>(u, p_nn, nnb, nnb + szNM, out_u, nullptr);
    // [9] proj2 (NPROD=3)
    gemm_mma<EPI_BIAS, 3, true, true, true><<<gD, 128, SM_TOTAL>>>(
        hb, hb + szNM, W2T, W2T + szDD, b2, p_zp, zpb, zpb + szNM, out_zproj, DDIM, DDIM,
        nullptr, nullptr);
    // [10] z_norm (bf split only) + fused loss_direct
    rownorm_split_kernel<<<NROWS, 256>>>(p_zp, nullptr, znb, znb + szNM, nullptr, p_nn);
    // [11] gate (NPROD=1)
    gemm_mma<EPI_SIGMOID, 1, true, false, false><<<gD, 128, SM_TOTAL>>>(
        zpb, zpb + szNM, WgT, WgT + szDD, bg, p_gate, nullptr, nullptr, nullptr, DDIM, DDIM,
        nullptr, nullptr);
    // [12] dual argmax + counts (NPROD=2)
    argmax_dual<<<NROWS / 128, 128, SM_TOTAL>>>(nnb, nnb + szNM,
                                                gdb, gdb + szGD, ldb, ldb + szLD, p_idx);
    // [13..15] scan / fill lists / gather dict update
    scan_kernel<<<1, 256>>>();
    fill_list_kernel<<<NROWS / 256, 256>>>(p_idx);
    dictupd_kernel<<<NCOMB, 256>>>(gd, ld, cbb, cbb + szCB);
    // [16] S = z_norm @ comb^T (NPROD=2; + fused sum|S|)
    gemm_mma<EPI_S_LOSS, 2, true, false, false><<<dim3(NCOMB / 128, NROWS / 128), 128, SM_TOTAL>>>(
        znb, znb + szNM, cbb, cbb + szCB, nullptr, p_S, nullptr, nullptr, nullptr, NCOMB, DDIM,
        nullptr, nullptr);
    // [17..18] softmax + comb^T
    softmax_split_kernel<<<NROWS, 256>>>(p_S, Sb, Sb + szNS);
    transconv_kernel<<<dim3(DDIM / 32, NCOMB / 32), 256>>>(p_comb, NCOMB, DDIM, ctb, ctb + szCB);
    // [19] weighted_u + fused z_clean (NPROD=1)
    gemm_mma<EPI_ZCLEAN, 1, true, false, false><<<gD, 128, SM_TOTAL>>>(
        Sb, Sb + szNS, ctb, ctb + szCB, nullptr, out_zc, nullptr, nullptr, nullptr, DDIM, NCOMB,
        z, p_gate);
    // [20] finalize loss
    finalize_kernel<<<1, 1>>>(out_loss);
}